// round 1
// baseline (speedup 1.0000x reference)
#include <cuda_runtime.h>
#include <math.h>

// Problem constants (fixed by reference)
#define LSEQ 4096
#define BATCH 32
#define MEMW 8      // MEM
#define PAD 15      // 2*MEM - 1

constexpr int TT  = 8;          // t values per block
constexpr int POS = TT + 14;    // window positions per batch: t0 .. t0+7+14

// scratch for co[t] (L x 2 floats), written by main kernel, read by broadcast
__device__ float g_co[LSEQ * 2];

// tid = m + 8*tl :  m = tid & 7 (memory tap), tl = tid >> 3 (local t)
__global__ __launch_bounds__(64) void gmp_main(const float* __restrict__ x,
                                               const float* __restrict__ Wr,
                                               const float* __restrict__ Wi) {
    __shared__ float4 tile[BATCH * POS];   // (u_re, u_im, |u|, 0) per (b,pos)

    const int tid = threadIdx.x;
    const int t0  = blockIdx.x * TT;

    // ---- stage all 32 batch windows into smem --------------------------
    for (int idx = tid; idx < BATCH * POS; idx += 64) {
        int b   = idx / POS;
        int pos = idx - b * POS;
        int xi  = t0 + pos - PAD;          // index into x along L (can be <0: zero pad)
        float ur = 0.f, ui = 0.f;
        if (xi >= 0) {                     // xi < LSEQ always holds (max 4094)
            float2 v = *reinterpret_cast<const float2*>(x + ((size_t)b * LSEQ + xi) * 2);
            ur = v.x; ui = v.y;
        }
        float a = sqrtf(fmaf(ur, ur, ui * ui));
        tile[idx] = make_float4(ur, ui, a, 0.f);
    }

    // ---- per-thread weights in registers (m fixed per thread) ----------
    const int m  = tid & 7;
    const int tl = tid >> 3;
    const float w0r = Wr[m * 41];
    const float w0i = Wi[m * 41];
    float wr[8][5], wi[8][5];
#pragma unroll
    for (int mp = 0; mp < 8; ++mp)
#pragma unroll
        for (int d = 0; d < 5; ++d) {
            wr[mp][d] = Wr[m * 41 + 1 + mp * 5 + d];
            wi[mp][d] = Wi[m * 41 + 1 + mp * 5 + d];
        }

    __syncthreads();

    // ---- main accumulation over batch ----------------------------------
    float accR = 0.f, accI = 0.f;
#pragma unroll 1
    for (int b = 0; b < BATCH; ++b) {
        const float4* base = &tile[b * POS + tl + m];
        float4 p0 = base[0];               // pos = t+m  (m'=0)
        const float umr = p0.x, umi = p0.y;
        float innR = w0r, innI = w0i;
#pragma unroll
        for (int mp = 0; mp < 8; ++mp) {
            float4 p = mp ? base[mp] : p0;
            float a = p.z;
            // polynomial part: c1 + a*(c2 + a*(c3 + a*c4))   (d = 1..4)
            float hr = fmaf(wr[mp][4], a, wr[mp][3]);
            hr = fmaf(hr, a, wr[mp][2]);
            hr = fmaf(hr, a, wr[mp][1]);
            float hi = fmaf(wi[mp][4], a, wi[mp][3]);
            hi = fmaf(hi, a, wi[mp][2]);
            hi = fmaf(hi, a, wi[mp][1]);
            // + W[m,1+5mp+0] * u(pos)   (complex * complex)
            hr = fmaf(wr[mp][0],  p.x, hr);
            hr = fmaf(-wi[mp][0], p.y, hr);
            hi = fmaf(wr[mp][0],  p.y, hi);
            hi = fmaf(wi[mp][0],  p.x, hi);
            innR += hr;
            innI += hi;
        }
        // acc += u[t+m] * inner  (complex)
        accR = fmaf(umr,  innR, accR);
        accR = fmaf(-umi, innI, accR);
        accI = fmaf(umr,  innI, accI);
        accI = fmaf(umi,  innR, accI);
    }

    // ---- reduce over m (8 lanes: xor 1,2,4 within warp) -----------------
#pragma unroll
    for (int o = 1; o < 8; o <<= 1) {
        accR += __shfl_xor_sync(0xffffffffu, accR, o);
        accI += __shfl_xor_sync(0xffffffffu, accI, o);
    }
    if (m == 0) {
        int t = t0 + tl;
        g_co[2 * t]     = accR;
        g_co[2 * t + 1] = accI;
    }
}

// broadcast co[t] -> out[b][t][2], float4 vectorized
__global__ void gmp_bcast(float4* __restrict__ out, int n4) {
    int i = blockIdx.x * blockDim.x + threadIdx.x;
    if (i < n4) {
        const float4* co4 = reinterpret_cast<const float4*>(g_co);
        out[i] = co4[i & ((LSEQ * 2 / 4) - 1)];   // i & 2047
    }
}

extern "C" void kernel_launch(void* const* d_in, const int* in_sizes, int n_in,
                              void* d_out, int out_size) {
    const float* x  = (const float*)d_in[0];
    // d_in[1] = h_0 : unused by reference
    const float* Wr = (const float*)d_in[2];
    const float* Wi = (const float*)d_in[3];

    gmp_main<<<LSEQ / TT, 64>>>(x, Wr, Wi);

    int n4 = out_size / 4;
    gmp_bcast<<<(n4 + 255) / 256, 256>>>((float4*)d_out, n4);
}

// round 2
// speedup vs baseline: 1.1380x; 1.1380x over previous
#include <cuda_runtime.h>
#include <math.h>

#define LSEQ  4096
#define BATCH 32
#define PAD   15          // 2*MEM - 1
#define POSN  22          // positions per batch window: tl+m+mp in [0,21]
#define STRIDE 23         // padded smem stride (odd -> no cross-b bank aliasing)
#define TT    8           // t values per block

// lane = m + 8*bq  (m: memory tap 0..7, bq: batch quarter 0..3), warp id = tl (0..7)
__global__ __launch_bounds__(256, 2)
void gmp_fused(const float* __restrict__ x,
               const float* __restrict__ Wr,
               const float* __restrict__ Wi,
               float2* __restrict__ out) {
    __shared__ float4 tile[BATCH * STRIDE];   // (u_re, u_im, |u|, 0)
    __shared__ float2 co_s[TT];

    const int tid = threadIdx.x;
    const int t0  = blockIdx.x * TT;

    // ---- stage all 32 batch windows (padded-index space) ----------------
    for (int idx = tid; idx < BATCH * POSN; idx += 256) {
        int b   = idx / POSN;
        int pos = idx - b * POSN;
        int xi  = t0 + pos - PAD;            // padded index -> zero for xi<0
        float ur = 0.f, ui = 0.f;
        if (xi >= 0) {
            float2 v = *reinterpret_cast<const float2*>(x + ((size_t)b * LSEQ + xi) * 2);
            ur = v.x; ui = v.y;
        }
        float a = sqrtf(fmaf(ur, ur, ui * ui));
        tile[b * STRIDE + pos] = make_float4(ur, ui, a, 0.f);
    }

    const int m  = tid & 7;
    const int bq = (tid >> 3) & 3;
    const int tl = tid >> 5;

    // ---- weights for this m in registers; fold constant (d=1) channel ---
    const float* wrm = Wr + m * 41;
    const float* wim = Wi + m * 41;
    float w0r = wrm[0];
    float w0i = wim[0];
    float wur[8], wui[8], w2r[8], w2i[8], w3r[8], w3i[8], w4r[8], w4i[8];
#pragma unroll
    for (int mp = 0; mp < 8; ++mp) {
        const int o = 1 + mp * 5;
        wur[mp] = wrm[o + 0];  wui[mp] = wim[o + 0];
        w0r    += wrm[o + 1];  w0i    += wim[o + 1];   // amp**0 == 1 channel
        w2r[mp] = wrm[o + 2];  w2i[mp] = wim[o + 2];
        w3r[mp] = wrm[o + 3];  w3i[mp] = wim[o + 3];
        w4r[mp] = wrm[o + 4];  w4i[mp] = wim[o + 4];
    }

    __syncthreads();

    // ---- 8 batches per thread (b = bq*8 + k) -----------------------------
    float accR = 0.f, accI = 0.f;
#pragma unroll 1
    for (int k = 0; k < 8; ++k) {
        const int b = bq * 8 + k;
        const float4* base = &tile[b * STRIDE + tl + m];
        const float4 p0 = base[0];
        float iR[2], iI[2];
        iR[0] = w0r; iI[0] = w0i; iR[1] = 0.f; iI[1] = 0.f;
#pragma unroll
        for (int mp = 0; mp < 8; ++mp) {
            const int c = mp & 1;               // alternate accumulators
            float4 p = base[mp];
            float a = p.z;
            float pr = fmaf(w4r[mp], a, w3r[mp]);
            pr = fmaf(pr, a, w2r[mp]);
            float pi = fmaf(w4i[mp], a, w3i[mp]);
            pi = fmaf(pi, a, w2i[mp]);
            iR[c] = fmaf(pr, a, iR[c]);
            iR[c] = fmaf(wur[mp],  p.x, iR[c]);
            iR[c] = fmaf(-wui[mp], p.y, iR[c]);
            iI[c] = fmaf(pi, a, iI[c]);
            iI[c] = fmaf(wur[mp],  p.y, iI[c]);
            iI[c] = fmaf(wui[mp],  p.x, iI[c]);
        }
        const float innR = iR[0] + iR[1];
        const float innI = iI[0] + iI[1];
        accR = fmaf(p0.x,  innR, accR);
        accR = fmaf(-p0.y, innI, accR);
        accI = fmaf(p0.x,  innI, accI);
        accI = fmaf(p0.y,  innR, accI);
    }

    // ---- full-warp reduce (m bits 0-2, bq bits 3-4) ----------------------
#pragma unroll
    for (int o = 1; o < 32; o <<= 1) {
        accR += __shfl_xor_sync(0xffffffffu, accR, o);
        accI += __shfl_xor_sync(0xffffffffu, accI, o);
    }
    if ((tid & 31) == 0) co_s[tl] = make_float2(accR, accI);
    __syncthreads();

    // ---- fused broadcast: out[b][t0+tt] for all 32 b ---------------------
    {
        const int b  = tid >> 3;
        const int tt = tid & 7;
        out[(size_t)b * LSEQ + t0 + tt] = co_s[tt];
    }
}

extern "C" void kernel_launch(void* const* d_in, const int* in_sizes, int n_in,
                              void* d_out, int out_size) {
    const float* x  = (const float*)d_in[0];
    // d_in[1] = h_0 : unused by the reference computation
    const float* Wr = (const float*)d_in[2];
    const float* Wi = (const float*)d_in[3];

    gmp_fused<<<LSEQ / TT, 256>>>(x, Wr, Wi, (float2*)d_out);
}

// round 4
// speedup vs baseline: 1.6000x; 1.4060x over previous
#include <cuda_runtime.h>
#include <math.h>

#define LSEQ 4096
#define PAD  15            // 2*MEM - 1
#define TT   16            // t per block
#define QN   23            // q = t+m range: TT + 7
#define POSN 30            // positions: QN + 7
#define TSTR 31            // tile row stride (float4), odd
#define GSTR 68            // G row stride (floats) = 17 float4

typedef unsigned long long ull;

__device__ __forceinline__ ull mul2(ull a, ull b) {
    ull r; asm("mul.rn.f32x2 %0, %1, %2;" : "=l"(r) : "l"(a), "l"(b)); return r;
}
__device__ __forceinline__ ull fma2(ull a, ull b, ull c) {
    ull r; asm("fma.rn.f32x2 %0, %1, %2, %3;" : "=l"(r) : "l"(a), "l"(b), "l"(c)); return r;
}
union F2U { ull u; float2 f; };

__global__ __launch_bounds__(256, 2)
void gmp_onepass(const float* __restrict__ x,
                 const float* __restrict__ Wr,
                 const float* __restrict__ Wi,
                 float* __restrict__ out) {
    __shared__ float4 tile[32 * TSTR];               // (a, a, ur, ui) per (b,pos), 16B aligned
    __shared__ __align__(16) float G[QN * GSTR];     // per q: 8 mp x {G0r,G0i,G2r,G2i, G3r,G3i,G4r,G4i}
    __shared__ float2 Ush[QN];                       // U(q) = sum_b u[b,q]
    __shared__ __align__(16) float2 co_s[TT];        // read back as float4
    __shared__ float  Wsh[2][8 * 41];

    const int tid = threadIdx.x;
    const int t0  = blockIdx.x * TT;

    // ---------- Phase A: stage weights + x window -------------------------
    for (int i = tid; i < 2 * 328; i += 256) {
        if (i < 328) Wsh[0][i] = Wr[i];
        else         Wsh[1][i - 328] = Wi[i - 328];
    }
    for (int idx = tid; idx < 32 * POSN; idx += 256) {
        int b   = idx / POSN;
        int pos = idx - b * POSN;
        int xi  = t0 + pos - PAD;          // padded coords; xi<0 -> zero
        float ur = 0.f, ui = 0.f;
        if (xi >= 0) {
            float2 v = *reinterpret_cast<const float2*>(x + ((size_t)b * LSEQ + xi) * 2);
            ur = v.x; ui = v.y;
        }
        float a = sqrtf(fmaf(ur, ur, ui * ui));
        tile[b * TSTR + pos] = make_float4(a, a, ur, ui);
    }
    __syncthreads();

    // ---------- Phase B: G[d,mp](q) = sum_b u[b,q] * ch_d[b,q+mp] ---------
    {
        const int mp = tid >> 5;          // warp id = lag
        const int q  = tid & 31;          // lane = q
        if (q < QN) {
            ull g2 = 0, g3 = 0, g4 = 0;   // packed (re,im) accumulators
            float g0r = 0.f, g0i = 0.f;
            float usr = 0.f, usi = 0.f;
#pragma unroll 8
            for (int b = 0; b < 32; ++b) {
                const float4* rb = tile + b * TSTR;
                F2U uq; uq.u = *reinterpret_cast<const ull*>(
                    reinterpret_cast<const float*>(rb + q) + 2);      // (ur,ui) at q, 8B-aligned
                ulonglong2 pp = *reinterpret_cast<const ulonglong2*>(rb + q + mp);  // 16B-aligned
                ull aa = pp.x;                                        // (a, a) at q+mp
                F2U up; up.u = pp.y;                                  // (ur,ui) at q+mp
                ull aa2 = mul2(aa, aa);
                ull aa3 = mul2(aa2, aa);
                g2 = fma2(uq.u, aa,  g2);
                g3 = fma2(uq.u, aa2, g3);
                g4 = fma2(uq.u, aa3, g4);
                g0r = fmaf(uq.f.x,  up.f.x, g0r);
                g0r = fmaf(-uq.f.y, up.f.y, g0r);
                g0i = fmaf(uq.f.x,  up.f.y, g0i);
                g0i = fmaf(uq.f.y,  up.f.x, g0i);
                if (mp == 0) { usr += uq.f.x; usi += uq.f.y; }
            }
            F2U g2f, g3f, g4f; g2f.u = g2; g3f.u = g3; g4f.u = g4;
            float* gq = G + q * GSTR + mp * 8;
            *reinterpret_cast<float4*>(gq)     = make_float4(g0r, g0i, g2f.f.x, g2f.f.y);
            *reinterpret_cast<float4*>(gq + 4) = make_float4(g3f.f.x, g3f.f.y, g4f.f.x, g4f.f.y);
            if (mp == 0) Ush[q] = make_float2(usr, usi);
        }
    }
    __syncthreads();

    // ---------- Phase C: co[t] = sum_m sum_mp sum_d c * G -----------------
    {
        const int m   = tid & 7;
        const int mph = (tid >> 3) & 1;
        const int tl  = tid >> 4;          // 0..15
        const int q   = tl + m;
        const float* wr = Wsh[0] + m * 41;
        const float* wi = Wsh[1] + m * 41;

        float accR = 0.f, accI = 0.f;
        if (mph == 0) {                    // W0'[m] * U(q)  (d=1 channel folded)
            float w0r = wr[0], w0i = wi[0];
#pragma unroll
            for (int mp = 0; mp < 8; ++mp) { w0r += wr[2 + 5 * mp]; w0i += wi[2 + 5 * mp]; }
            float2 Uq = Ush[q];
            accR = fmaf(w0r, Uq.x, accR); accR = fmaf(-w0i, Uq.y, accR);
            accI = fmaf(w0r, Uq.y, accI); accI = fmaf(w0i, Uq.x, accI);
        }
#pragma unroll
        for (int j = 0; j < 4; ++j) {
            const int mp = mph * 4 + j;
            const float* gq = G + q * GSTR + mp * 8;
            float4 gA = *reinterpret_cast<const float4*>(gq);
            float4 gB = *reinterpret_cast<const float4*>(gq + 4);
            const int o = 1 + 5 * mp;
            float wur = wr[o],     wui = wi[o];
            float c2r = wr[o + 2], c2i = wi[o + 2];
            float c3r = wr[o + 3], c3i = wi[o + 3];
            float c4r = wr[o + 4], c4i = wi[o + 4];
            accR = fmaf(wur,  gA.x, accR); accR = fmaf(-wui, gA.y, accR);
            accI = fmaf(wur,  gA.y, accI); accI = fmaf(wui,  gA.x, accI);
            accR = fmaf(c2r,  gA.z, accR); accR = fmaf(-c2i, gA.w, accR);
            accI = fmaf(c2r,  gA.w, accI); accI = fmaf(c2i,  gA.z, accI);
            accR = fmaf(c3r,  gB.x, accR); accR = fmaf(-c3i, gB.y, accR);
            accI = fmaf(c3r,  gB.y, accI); accI = fmaf(c3i,  gB.x, accI);
            accR = fmaf(c4r,  gB.z, accR); accR = fmaf(-c4i, gB.w, accR);
            accI = fmaf(c4r,  gB.w, accI); accI = fmaf(c4i,  gB.z, accI);
        }
        // reduce over m (bits 0-2) and mph (bit 3)
#pragma unroll
        for (int o = 1; o < 16; o <<= 1) {
            accR += __shfl_xor_sync(0xffffffffu, accR, o);
            accI += __shfl_xor_sync(0xffffffffu, accI, o);
        }
        if ((tid & 15) == 0) co_s[tl] = make_float2(accR, accI);
    }
    __syncthreads();

    // ---------- fused broadcast: out[b][t0..t0+15] for all b --------------
    {
        const int b = tid >> 3;
        const int f = tid & 7;
        const float4* c4 = reinterpret_cast<const float4*>(co_s);
        reinterpret_cast<float4*>(out + ((size_t)b * LSEQ + t0) * 2)[f] = c4[f];
    }
}

extern "C" void kernel_launch(void* const* d_in, const int* in_sizes, int n_in,
                              void* d_out, int out_size) {
    const float* x  = (const float*)d_in[0];
    // d_in[1] = h_0 : unused by the reference computation
    const float* Wr = (const float*)d_in[2];
    const float* Wi = (const float*)d_in[3];

    gmp_onepass<<<LSEQ / TT, 256>>>(x, Wr, Wi, (float*)d_out);
}